// round 4
// baseline (speedup 1.0000x reference)
#include <cuda_runtime.h>

// Problem constants
#define B_      64
#define CIN     64
#define COUT    64
#define KP      3
#define T_      300
#define V_      25
#define TT      12           // timesteps per block
#define NCHUNK  (T_/TT)      // 25 chunks
#define NTHREADS 192         // 16 c-groups x 12 t
#define NBLK    (B_*NCHUNK)  // 1600 blocks
#define NPIX    (B_*T_*V_)   // 480000 elements per channel (BN population)

// Padded smem x row: 28 floats per timestep row (16B-aligned float4 chunks)
#define PADV    28
#define XROW    (TT*PADV)    // 336 floats per ci
#define WSTRIDE 68           // padded W row (floats); 68*4B % 16 == 0

// Dynamic smem layout (floats)
#define XS_OFF  0                        // 64*336      = 21504
#define WS_OFF  (XS_OFF + CIN*XROW)      // 64*68       =  4352
#define AS_OFF  (WS_OFF + COUT*WSTRIDE)  // 3*25*25     =  1875
#define SMEM_FLOATS (AS_OFF + KP*V_*V_)  // 27731 floats = 110924 B (~108.3 KB)
// BN reduce buffer (64*12*2 = 1536 floats) aliases the dead W tile region.

// Deterministic BN scratch
__device__ float g_part_sum[NBLK*COUT];
__device__ float g_part_sq [NBLK*COUT];
__device__ float g_scale   [COUT];
__device__ float g_shift   [COUT];

extern __shared__ float smem[];

// ---------------------------------------------------------------------------
// Kernel 1: fused 1x1-conv + per-partition graph matmul + BN partial stats
// ---------------------------------------------------------------------------
__global__ __launch_bounds__(NTHREADS, 2)
void sgc_fused_kernel(const float* __restrict__ x,
                      const float* __restrict__ Wg,
                      const float* __restrict__ bias,
                      const float* __restrict__ Ag,
                      float* __restrict__ out)
{
    float* xs  = smem + XS_OFF;
    float* ws  = smem + WS_OFF;
    float* As  = smem + AS_OFF;
    float* red = smem + WS_OFF;   // alias: reused after main loop

    const int tid   = threadIdx.x;
    const int chunk = blockIdx.x;     // 0..24
    const int b     = blockIdx.y;     // 0..63
    const int t0    = chunk * TT;
    const int cg    = tid & 15;       // c-group: channels cg*4 .. cg*4+3
    const int tq    = tid >> 4;       // local timestep 0..11

    // ---- stage x tile (padded rows): xs[ci*336 + t*28 + v] ----
    {
        const float* xbase = x + (size_t)b * (CIN * T_ * V_) + t0 * V_;
        #pragma unroll 4
        for (int i = tid; i < CIN * TT * V_; i += NTHREADS) {
            int ci = i / (TT * V_);
            int p  = i - ci * (TT * V_);
            int t  = p / V_;
            int v  = p - t * V_;
            xs[ci * XROW + t * PADV + v] = xbase[ci * (T_ * V_) + p];
        }
    }
    // ---- stage A ----
    for (int i = tid; i < KP * V_ * V_; i += NTHREADS) As[i] = Ag[i];

    // Output accumulator in registers: 4 channels x 25 w
    float oacc[4][V_];
    #pragma unroll
    for (int j = 0; j < 4; ++j)
        #pragma unroll
        for (int w = 0; w < V_; ++w) oacc[j][w] = 0.0f;

    const float* xrow = xs + tq * PADV;     // this thread's timestep row base

    #pragma unroll 1
    for (int k = 0; k < KP; ++k) {
        // stage W partition k transposed: ws[ci*68 + c] = W[(k*64+c)*64 + ci]
        __syncthreads();
        {
            const float* wsrc = Wg + k * (COUT * CIN);
            #pragma unroll 4
            for (int i = tid; i < COUT * CIN; i += NTHREADS) {
                int c  = i >> 6;
                int ci = i & 63;
                ws[ci * WSTRIDE + c] = wsrc[i];
            }
        }
        __syncthreads();

        const float b0 = bias[k * COUT + cg * 4 + 0];
        const float b1 = bias[k * COUT + cg * 4 + 1];
        const float b2 = bias[k * COUT + cg * 4 + 2];
        const float b3 = bias[k * COUT + cg * 4 + 3];
        const float* Ak = As + k * (V_ * V_);

        // ---- v in aligned chunks of 4, plus scalar remainder v=24 (vc=6) ----
        #pragma unroll 1
        for (int vc = 0; vc < 7; ++vc) {
            const int v0 = vc * 4;
            if (v0 < 24) {
                // y[c] = float4 over vv = v0..v0+3
                float4 y0 = make_float4(b0, b0, b0, b0);
                float4 y1 = make_float4(b1, b1, b1, b1);
                float4 y2 = make_float4(b2, b2, b2, b2);
                float4 y3 = make_float4(b3, b3, b3, b3);
                #pragma unroll 2
                for (int ci = 0; ci < CIN; ++ci) {
                    const float4 wv = *(const float4*)(ws + ci * WSTRIDE + cg * 4);
                    const float4 xv = *(const float4*)(xrow + ci * XROW + v0);
                    y0.x += wv.x * xv.x; y0.y += wv.x * xv.y; y0.z += wv.x * xv.z; y0.w += wv.x * xv.w;
                    y1.x += wv.y * xv.x; y1.y += wv.y * xv.y; y1.z += wv.y * xv.z; y1.w += wv.y * xv.w;
                    y2.x += wv.z * xv.x; y2.y += wv.z * xv.y; y2.z += wv.z * xv.z; y2.w += wv.z * xv.w;
                    y3.x += wv.w * xv.x; y3.y += wv.w * xv.y; y3.z += wv.w * xv.z; y3.w += wv.w * xv.w;
                }
                // graph stage: oacc[c][w] += sum_vv y[c][vv] * A[k, v0+vv, w]
                #pragma unroll
                for (int w = 0; w < V_; ++w) {
                    const float a0 = Ak[(v0 + 0) * V_ + w];
                    const float a1 = Ak[(v0 + 1) * V_ + w];
                    const float a2 = Ak[(v0 + 2) * V_ + w];
                    const float a3 = Ak[(v0 + 3) * V_ + w];
                    oacc[0][w] += y0.x * a0 + y0.y * a1 + y0.z * a2 + y0.w * a3;
                    oacc[1][w] += y1.x * a0 + y1.y * a1 + y1.z * a2 + y1.w * a3;
                    oacc[2][w] += y2.x * a0 + y2.y * a1 + y2.z * a2 + y2.w * a3;
                    oacc[3][w] += y3.x * a0 + y3.y * a1 + y3.z * a2 + y3.w * a3;
                }
            } else {
                // remainder v = 24
                float y0 = b0, y1 = b1, y2 = b2, y3 = b3;
                #pragma unroll 2
                for (int ci = 0; ci < CIN; ++ci) {
                    const float4 wv = *(const float4*)(ws + ci * WSTRIDE + cg * 4);
                    const float xv = xrow[ci * XROW + 24];
                    y0 += wv.x * xv; y1 += wv.y * xv; y2 += wv.z * xv; y3 += wv.w * xv;
                }
                #pragma unroll
                for (int w = 0; w < V_; ++w) {
                    const float a = Ak[24 * V_ + w];
                    oacc[0][w] += y0 * a;
                    oacc[1][w] += y1 * a;
                    oacc[2][w] += y2 * a;
                    oacc[3][w] += y3 * a;
                }
            }
        }
    }

    // ---- write pre-BN output directly from registers ----
    {
        const int t = t0 + tq;
        #pragma unroll
        for (int j = 0; j < 4; ++j) {
            float* dst = out + ((size_t)(b * COUT + cg * 4 + j) * T_ + t) * V_;
            #pragma unroll
            for (int w = 0; w < V_; ++w) dst[w] = oacc[j][w];
        }
    }

    // ---- per-block per-channel partial BN stats (deterministic) ----
    __syncthreads();   // all reads of ws done before aliased red writes
    #pragma unroll
    for (int j = 0; j < 4; ++j) {
        float s = 0.0f, s2 = 0.0f;
        #pragma unroll
        for (int w = 0; w < V_; ++w) {
            const float v = oacc[j][w];
            s += v; s2 += v * v;
        }
        const int c = cg * 4 + j;
        red[(c * TT + tq) * 2 + 0] = s;
        red[(c * TT + tq) * 2 + 1] = s2;
    }
    __syncthreads();
    if (tid < COUT) {
        const int c = tid;
        float s = 0.0f, s2 = 0.0f;
        #pragma unroll
        for (int q = 0; q < TT; ++q) {
            s  += red[(c * TT + q) * 2 + 0];
            s2 += red[(c * TT + q) * 2 + 1];
        }
        const int blk = b * NCHUNK + chunk;
        g_part_sum[blk * COUT + c] = s;
        g_part_sq [blk * COUT + c] = s2;
    }
}

// ---------------------------------------------------------------------------
// Kernel 2: finalize BN stats (one block per channel, deterministic tree)
// ---------------------------------------------------------------------------
__global__ void sgc_stats_kernel(const float* __restrict__ gamma,
                                 const float* __restrict__ beta)
{
    __shared__ float ss[256];
    __shared__ float ss2[256];
    const int c = blockIdx.x;
    float s = 0.0f, s2 = 0.0f;
    for (int i = threadIdx.x; i < NBLK; i += 256) {
        s  += g_part_sum[i * COUT + c];
        s2 += g_part_sq [i * COUT + c];
    }
    ss[threadIdx.x] = s;
    ss2[threadIdx.x] = s2;
    __syncthreads();
    for (int o = 128; o > 0; o >>= 1) {
        if (threadIdx.x < o) {
            ss[threadIdx.x]  += ss[threadIdx.x + o];
            ss2[threadIdx.x] += ss2[threadIdx.x + o];
        }
        __syncthreads();
    }
    if (threadIdx.x == 0) {
        const float n    = (float)NPIX;
        const float mean = ss[0] / n;
        const float var  = ss2[0] / n - mean * mean;   // biased variance
        const float inv  = rsqrtf(var + 1e-5f);
        const float sc   = gamma[c] * inv;
        g_scale[c] = sc;
        g_shift[c] = beta[c] - mean * sc;
    }
}

// ---------------------------------------------------------------------------
// Kernel 3: in-place normalize, float4 vectorized (7500 % 4 == 0)
// ---------------------------------------------------------------------------
__global__ void sgc_norm_kernel(float* __restrict__ out)
{
    const int i4 = blockIdx.x * blockDim.x + threadIdx.x;  // exactly 7,680,000
    float4* o4 = (float4*)out;
    float4 v = o4[i4];
    const int c = (i4 / (T_ * V_ / 4)) & (COUT - 1);
    const float sc = g_scale[c];
    const float sh = g_shift[c];
    v.x = v.x * sc + sh;
    v.y = v.y * sc + sh;
    v.z = v.z * sc + sh;
    v.w = v.w * sc + sh;
    o4[i4] = v;
}

// ---------------------------------------------------------------------------
extern "C" void kernel_launch(void* const* d_in, const int* in_sizes, int n_in,
                              void* d_out, int out_size)
{
    const float* x     = (const float*)d_in[0];
    const float* W     = (const float*)d_in[1];
    const float* bias  = (const float*)d_in[2];
    const float* A     = (const float*)d_in[3];
    const float* gamma = (const float*)d_in[4];
    const float* beta  = (const float*)d_in[5];
    float* out = (float*)d_out;

    const int smem_bytes = SMEM_FLOATS * (int)sizeof(float);  // ~108.3 KB
    cudaFuncSetAttribute(sgc_fused_kernel,
                         cudaFuncAttributeMaxDynamicSharedMemorySize, smem_bytes);
    cudaFuncSetAttribute(sgc_fused_kernel,
                         cudaFuncAttributePreferredSharedMemoryCarveout, 100);

    sgc_fused_kernel<<<dim3(NCHUNK, B_), NTHREADS, smem_bytes>>>(x, W, bias, A, out);
    sgc_stats_kernel<<<COUT, 256>>>(gamma, beta);
    sgc_norm_kernel<<<30000, 256>>>(out);
}

// round 6
// speedup vs baseline: 1.0028x; 1.0028x over previous
#include <cuda_runtime.h>

// Problem constants
#define B_      64
#define CIN     64
#define COUT    64
#define KP      3
#define T_      300
#define V_      25
#define TT      12           // timesteps per block
#define NCHUNK  (T_/TT)      // 25 chunks
#define NTHREADS 192         // 16 c-groups x 12 t
#define NBLK    (B_*NCHUNK)  // 1600 blocks
#define NPIX    (B_*T_*V_)   // 480000 elements per channel (BN population)

// Padded smem x row: 28 floats per timestep row (16B-aligned float4 chunks)
#define PADV    28
#define XROW    (TT*PADV)    // 336 floats per ci
#define WSTRIDE 68           // padded W row (floats); 68*4B % 16 == 0

// Dynamic smem layout (floats)
#define XS_OFF  0                        // 64*336      = 21504
#define WS_OFF  (XS_OFF + CIN*XROW)      // 64*68       =  4352
#define AS_OFF  (WS_OFF + COUT*WSTRIDE)  // 3*25*25     =  1875
#define SMEM_FLOATS (AS_OFF + KP*V_*V_)  // 27731 floats = 110924 B (~108.3 KB)
// BN reduce buffer (64*12*2 = 1536 floats) aliases the dead W tile region.

// Deterministic BN scratch
__device__ float g_part_sum[NBLK*COUT];
__device__ float g_part_sq [NBLK*COUT];
__device__ float g_scale   [COUT];
__device__ float g_shift   [COUT];

extern __shared__ float smem[];

// ---------------------------------------------------------------------------
// Kernel 1: fused 1x1-conv + per-partition graph matmul + BN partial stats
// ---------------------------------------------------------------------------
__global__ __launch_bounds__(NTHREADS, 2)
void sgc_fused_kernel(const float* __restrict__ x,
                      const float* __restrict__ Wg,
                      const float* __restrict__ bias,
                      const float* __restrict__ Ag,
                      float* __restrict__ out)
{
    float* xs  = smem + XS_OFF;
    float* ws  = smem + WS_OFF;
    float* As  = smem + AS_OFF;
    float* red = smem + WS_OFF;   // alias: reused after main loop

    const int tid   = threadIdx.x;
    const int chunk = blockIdx.x;     // 0..24
    const int b     = blockIdx.y;     // 0..63
    const int t0    = chunk * TT;
    const int cg    = tid & 15;       // c-group: channels cg*4 .. cg*4+3
    const int tq    = tid >> 4;       // local timestep 0..11

    // ---- stage x tile (padded rows): xs[ci*336 + t*28 + v] ----
    {
        const float* xbase = x + (size_t)b * (CIN * T_ * V_) + t0 * V_;
        #pragma unroll 4
        for (int i = tid; i < CIN * TT * V_; i += NTHREADS) {
            int ci = i / (TT * V_);
            int p  = i - ci * (TT * V_);
            int t  = p / V_;
            int v  = p - t * V_;
            xs[ci * XROW + t * PADV + v] = xbase[ci * (T_ * V_) + p];
        }
    }
    // ---- stage A ----
    for (int i = tid; i < KP * V_ * V_; i += NTHREADS) As[i] = Ag[i];

    // Output accumulator in registers: 4 channels x 25 w
    float oacc[4][V_];
    #pragma unroll
    for (int j = 0; j < 4; ++j)
        #pragma unroll
        for (int w = 0; w < V_; ++w) oacc[j][w] = 0.0f;

    const float* xrow = xs + tq * PADV;     // this thread's timestep row base

    #pragma unroll 1
    for (int k = 0; k < KP; ++k) {
        // stage W partition k transposed: ws[ci*68 + c] = W[(k*64+c)*64 + ci]
        __syncthreads();
        {
            const float* wsrc = Wg + k * (COUT * CIN);
            #pragma unroll 4
            for (int i = tid; i < COUT * CIN; i += NTHREADS) {
                int c  = i >> 6;
                int ci = i & 63;
                ws[ci * WSTRIDE + c] = wsrc[i];
            }
        }
        __syncthreads();

        const float b0 = bias[k * COUT + cg * 4 + 0];
        const float b1 = bias[k * COUT + cg * 4 + 1];
        const float b2 = bias[k * COUT + cg * 4 + 2];
        const float b3 = bias[k * COUT + cg * 4 + 3];
        const float* Ak = As + k * (V_ * V_);

        // ---- v in aligned chunks of 4, plus scalar remainder v=24 (vc=6) ----
        #pragma unroll 1
        for (int vc = 0; vc < 7; ++vc) {
            const int v0 = vc * 4;
            if (v0 < 24) {
                // y[c] = float4 over vv = v0..v0+3
                float4 y0 = make_float4(b0, b0, b0, b0);
                float4 y1 = make_float4(b1, b1, b1, b1);
                float4 y2 = make_float4(b2, b2, b2, b2);
                float4 y3 = make_float4(b3, b3, b3, b3);
                #pragma unroll 2
                for (int ci = 0; ci < CIN; ++ci) {
                    const float4 wv = *(const float4*)(ws + ci * WSTRIDE + cg * 4);
                    const float4 xv = *(const float4*)(xrow + ci * XROW + v0);
                    y0.x += wv.x * xv.x; y0.y += wv.x * xv.y; y0.z += wv.x * xv.z; y0.w += wv.x * xv.w;
                    y1.x += wv.y * xv.x; y1.y += wv.y * xv.y; y1.z += wv.y * xv.z; y1.w += wv.y * xv.w;
                    y2.x += wv.z * xv.x; y2.y += wv.z * xv.y; y2.z += wv.z * xv.z; y2.w += wv.z * xv.w;
                    y3.x += wv.w * xv.x; y3.y += wv.w * xv.y; y3.z += wv.w * xv.z; y3.w += wv.w * xv.w;
                }
                // graph stage: oacc[c][w] += sum_vv y[c][vv] * A[k, v0+vv, w]
                #pragma unroll
                for (int w = 0; w < V_; ++w) {
                    const float a0 = Ak[(v0 + 0) * V_ + w];
                    const float a1 = Ak[(v0 + 1) * V_ + w];
                    const float a2 = Ak[(v0 + 2) * V_ + w];
                    const float a3 = Ak[(v0 + 3) * V_ + w];
                    oacc[0][w] += y0.x * a0 + y0.y * a1 + y0.z * a2 + y0.w * a3;
                    oacc[1][w] += y1.x * a0 + y1.y * a1 + y1.z * a2 + y1.w * a3;
                    oacc[2][w] += y2.x * a0 + y2.y * a1 + y2.z * a2 + y2.w * a3;
                    oacc[3][w] += y3.x * a0 + y3.y * a1 + y3.z * a2 + y3.w * a3;
                }
            } else {
                // remainder v = 24
                float y0 = b0, y1 = b1, y2 = b2, y3 = b3;
                #pragma unroll 2
                for (int ci = 0; ci < CIN; ++ci) {
                    const float4 wv = *(const float4*)(ws + ci * WSTRIDE + cg * 4);
                    const float xv = xrow[ci * XROW + 24];
                    y0 += wv.x * xv; y1 += wv.y * xv; y2 += wv.z * xv; y3 += wv.w * xv;
                }
                #pragma unroll
                for (int w = 0; w < V_; ++w) {
                    const float a = Ak[24 * V_ + w];
                    oacc[0][w] += y0 * a;
                    oacc[1][w] += y1 * a;
                    oacc[2][w] += y2 * a;
                    oacc[3][w] += y3 * a;
                }
            }
        }
    }

    // ---- write pre-BN output directly from registers ----
    {
        const int t = t0 + tq;
        #pragma unroll
        for (int j = 0; j < 4; ++j) {
            float* dst = out + ((size_t)(b * COUT + cg * 4 + j) * T_ + t) * V_;
            #pragma unroll
            for (int w = 0; w < V_; ++w) dst[w] = oacc[j][w];
        }
    }

    // ---- per-block per-channel partial BN stats (deterministic) ----
    __syncthreads();   // all reads of ws done before aliased red writes
    #pragma unroll
    for (int j = 0; j < 4; ++j) {
        float s = 0.0f, s2 = 0.0f;
        #pragma unroll
        for (int w = 0; w < V_; ++w) {
            const float v = oacc[j][w];
            s += v; s2 += v * v;
        }
        const int c = cg * 4 + j;
        red[(c * TT + tq) * 2 + 0] = s;
        red[(c * TT + tq) * 2 + 1] = s2;
    }
    __syncthreads();
    if (tid < COUT) {
        const int c = tid;
        float s = 0.0f, s2 = 0.0f;
        #pragma unroll
        for (int q = 0; q < TT; ++q) {
            s  += red[(c * TT + q) * 2 + 0];
            s2 += red[(c * TT + q) * 2 + 1];
        }
        const int blk = b * NCHUNK + chunk;
        g_part_sum[blk * COUT + c] = s;
        g_part_sq [blk * COUT + c] = s2;
    }
}

// ---------------------------------------------------------------------------
// Kernel 2: finalize BN stats (one block per channel, deterministic tree)
// ---------------------------------------------------------------------------
__global__ void sgc_stats_kernel(const float* __restrict__ gamma,
                                 const float* __restrict__ beta)
{
    __shared__ float ss[256];
    __shared__ float ss2[256];
    const int c = blockIdx.x;
    float s = 0.0f, s2 = 0.0f;
    for (int i = threadIdx.x; i < NBLK; i += 256) {
        s  += g_part_sum[i * COUT + c];
        s2 += g_part_sq [i * COUT + c];
    }
    ss[threadIdx.x] = s;
    ss2[threadIdx.x] = s2;
    __syncthreads();
    for (int o = 128; o > 0; o >>= 1) {
        if (threadIdx.x < o) {
            ss[threadIdx.x]  += ss[threadIdx.x + o];
            ss2[threadIdx.x] += ss2[threadIdx.x + o];
        }
        __syncthreads();
    }
    if (threadIdx.x == 0) {
        const float n    = (float)NPIX;
        const float mean = ss[0] / n;
        const float var  = ss2[0] / n - mean * mean;   // biased variance
        const float inv  = rsqrtf(var + 1e-5f);
        const float sc   = gamma[c] * inv;
        g_scale[c] = sc;
        g_shift[c] = beta[c] - mean * sc;
    }
}

// ---------------------------------------------------------------------------
// Kernel 3: in-place normalize, float4 vectorized (7500 % 4 == 0)
// ---------------------------------------------------------------------------
__global__ void sgc_norm_kernel(float* __restrict__ out)
{
    const int i4 = blockIdx.x * blockDim.x + threadIdx.x;  // exactly 7,680,000
    float4* o4 = (float4*)out;
    float4 v = o4[i4];
    const int c = (i4 / (T_ * V_ / 4)) & (COUT - 1);
    const float sc = g_scale[c];
    const float sh = g_shift[c];
    v.x = v.x * sc + sh;
    v.y = v.y * sc + sh;
    v.z = v.z * sc + sh;
    v.w = v.w * sc + sh;
    o4[i4] = v;
}

// ---------------------------------------------------------------------------
extern "C" void kernel_launch(void* const* d_in, const int* in_sizes, int n_in,
                              void* d_out, int out_size)
{
    const float* x     = (const float*)d_in[0];
    const float* W     = (const float*)d_in[1];
    const float* bias  = (const float*)d_in[2];
    const float* A     = (const float*)d_in[3];
    const float* gamma = (const float*)d_in[4];
    const float* beta  = (const float*)d_in[5];
    float* out = (float*)d_out;

    const int smem_bytes = SMEM_FLOATS * (int)sizeof(float);  // ~108.3 KB
    cudaFuncSetAttribute(sgc_fused_kernel,
                         cudaFuncAttributeMaxDynamicSharedMemorySize, smem_bytes);
    cudaFuncSetAttribute(sgc_fused_kernel,
                         cudaFuncAttributePreferredSharedMemoryCarveout, 100);

    sgc_fused_kernel<<<dim3(NCHUNK, B_), NTHREADS, smem_bytes>>>(x, W, bias, A, out);
    sgc_stats_kernel<<<COUT, 256>>>(gamma, beta);
    sgc_norm_kernel<<<30000, 256>>>(out);
}